// round 5
// baseline (speedup 1.0000x reference)
#include <cuda_runtime.h>

#define NC 4096
#define NA 2048
#define NB (NC + NA)          // 6144 bodies
#define TPB 128
#define ITILES (NB / TPB)     // 48 i-tiles
#define SUB 256               // j sub-chunk size
#define NSUB 4                // sub-chunks per block
#define JBIG (SUB * NSUB)     // 1024 j per block
#define NJY 6                 // 4 circle groups (4096) + 2 aabb groups (2048)
#define EPSF 1e-9f

// partial corrections: [NJY][NB*2]
__device__ float g_partial[NJY * NB * 2];

__device__ __forceinline__ float rsq_approx(float x) {
    float r;
    asm("rsqrt.approx.f32 %0, %1;" : "=f"(r) : "f"(x));
    return r;
}

__global__ void __launch_bounds__(TPB)
collide_kernel(const float* __restrict__ cpos, const float* __restrict__ crad,
               const float* __restrict__ apos, const float* __restrict__ ahalf)
{
    __shared__ float4 sj[SUB];   // (x, y, r_or_hx, hy)

    const int tid = threadIdx.x;
    const int i   = blockIdx.x * TPB + tid;          // body index 0..NB-1
    const bool i_is_circle = (i < NC);
    const int jy = blockIdx.y;
    const bool j_is_circle = (jy < 4);
    const int jbase = j_is_circle ? (jy * JBIG) : ((jy - 4) * JBIG);

    // hoisted i-state (registers for whole 1024-j loop)
    float pix, piy, ra, rb;      // circle: ra=r, rb=r^2 ; aabb: ra=hx, rb=hy
    int   ia = 0;
    if (i_is_circle) {
        float2 p = ((const float2*)cpos)[i];
        pix = p.x; piy = p.y;
        ra = crad[i]; rb = ra * ra;
    } else {
        ia = i - NC;
        float2 p = ((const float2*)apos)[ia];
        float2 h = ((const float2*)ahalf)[ia];
        pix = p.x; piy = p.y;
        ra = h.x; rb = h.y;
    }

    float cx = 0.0f, cy = 0.0f;

    #pragma unroll 1
    for (int c = 0; c < NSUB; c++) {
        const int j0 = jbase + c * SUB;
        __syncthreads();   // previous sub-chunk fully consumed
        // stage SUB bodies (each thread loads 2)
        #pragma unroll
        for (int t = tid; t < SUB; t += TPB) {
            if (j_is_circle) {
                float2 p = ((const float2*)cpos)[j0 + t];
                sj[t] = make_float4(p.x, p.y, crad[j0 + t], 0.0f);
            } else {
                float2 p = ((const float2*)apos)[j0 + t];
                float2 h = ((const float2*)ahalf)[j0 + t];
                sj[t] = make_float4(p.x, p.y, h.x, h.y);
            }
        }
        __syncthreads();

        if (i_is_circle) {
            if (j_is_circle) {
                // circle vs circle
                #pragma unroll 8
                for (int k = 0; k < SUB; k++) {
                    float4 b = sj[k];
                    float dx = pix - b.x;
                    float dy = piy - b.y;
                    float d2 = fmaf(dx, dx, dy * dy);
                    float rsum = ra + b.z;
                    float inv = rsq_approx(d2);
                    float s = fmaf(0.5f * rsum, inv, -0.5f);   // 0.5*(rsum-dist)/dist
                    bool hit = (d2 > EPSF) && (d2 < rsum * rsum);
                    s = hit ? s : 0.0f;
                    cx = fmaf(s, dx, cx);
                    cy = fmaf(s, dy, cy);
                }
            } else {
                // circle vs aabb (push on circle)
                #pragma unroll 8
                for (int k = 0; k < SUB; k++) {
                    float4 b = sj[k];
                    float relx = pix - b.x;
                    float rely = piy - b.y;
                    float qx = fminf(fmaxf(relx, -b.z), b.z);
                    float qy = fminf(fmaxf(rely, -b.w), b.w);
                    float dx = relx - qx;
                    float dy = rely - qy;
                    float dd2 = fmaf(dx, dx, dy * dy);
                    float inv = rsq_approx(dd2);
                    float s = fmaf(0.5f * ra, inv, -0.5f);
                    bool hit = (dd2 > EPSF) && (dd2 < rb);     // rb = ri^2
                    s = hit ? s : 0.0f;
                    cx = fmaf(s, dx, cx);
                    cy = fmaf(s, dy, cy);
                }
            }
        } else {
            if (j_is_circle) {
                // aabb vs circle (equal-and-opposite push on aabb)
                #pragma unroll 8
                for (int k = 0; k < SUB; k++) {
                    float4 b = sj[k];
                    float relx = b.x - pix;          // circle - aabb
                    float rely = b.y - piy;
                    float qx = fminf(fmaxf(relx, -ra), ra);   // ra=hx
                    float qy = fminf(fmaxf(rely, -rb), rb);   // rb=hy
                    float dx = relx - qx;
                    float dy = rely - qy;
                    float dd2 = fmaf(dx, dx, dy * dy);
                    float rj = b.z;
                    float inv = rsq_approx(dd2);
                    float s = fmaf(0.5f * rj, inv, -0.5f);
                    bool hit = (dd2 > EPSF) && (dd2 < rj * rj);
                    s = hit ? -s : 0.0f;             // negated: push on the box
                    cx = fmaf(s, dx, cx);
                    cy = fmaf(s, dy, cy);
                }
            } else {
                // aabb vs aabb
                #pragma unroll 8
                for (int k = 0; k < SUB; k++) {
                    float4 b = sj[k];
                    int j = j0 + k;
                    float dax = pix - b.x;
                    float day = piy - b.y;
                    float ovx = (ra + b.z) - fabsf(dax);
                    float ovy = (rb + b.w) - fabsf(day);
                    bool hit = (ovx > 0.0f) && (ovy > 0.0f) && (ia != j);
                    bool usex = (ovx <= ovy);
                    float px = copysignf(0.5f * ovx, dax);   // sgn(+0)=+1 matches da>=0
                    float py = copysignf(0.5f * ovy, day);
                    cx += (hit && usex)  ? px : 0.0f;
                    cy += (hit && !usex) ? py : 0.0f;
                }
            }
        }
    }

    float2* part = (float2*)&g_partial[(size_t)jy * (NB * 2)];
    part[i] = make_float2(cx, cy);
}

__global__ void __launch_bounds__(TPB)
reduce_kernel(const float* __restrict__ cpos, const float* __restrict__ apos,
              float* __restrict__ out)
{
    const int idx = blockIdx.x * TPB + threadIdx.x;   // 0 .. NB*2-1
    if (idx >= NB * 2) return;
    float base = (idx < 2 * NC) ? cpos[idx] : apos[idx - 2 * NC];
    float acc = 0.0f;
    #pragma unroll
    for (int y = 0; y < NJY; y++) {
        acc += g_partial[(size_t)y * (NB * 2) + idx];
    }
    out[idx] = base + acc;
}

extern "C" void kernel_launch(void* const* d_in, const int* in_sizes, int n_in,
                              void* d_out, int out_size)
{
    const float* cpos  = (const float*)d_in[0];   // [4096,2]
    const float* crad  = (const float*)d_in[1];   // [4096]
    const float* apos  = (const float*)d_in[2];   // [2048,2]
    const float* ahalf = (const float*)d_in[3];   // [2048,2]
    float* out = (float*)d_out;                   // [6144,2]

    dim3 grid(ITILES, NJY);
    collide_kernel<<<grid, TPB>>>(cpos, crad, apos, ahalf);
    reduce_kernel<<<(NB * 2 + TPB - 1) / TPB, TPB>>>(cpos, apos, out);
}

// round 6
// speedup vs baseline: 1.3034x; 1.3034x over previous
#include <cuda_runtime.h>

#define NC 4096
#define NA 2048
#define NB (NC + NA)          // 6144 bodies
#define TPB 256
#define ITILES (NB / TPB)     // 24 i-tiles
#define NCY (NC / TPB)        // 16 circle j-chunks
#define NAY (NA / TPB)        // 8 aabb j-chunks
#define NJY (NCY + NAY)       // 24 j-chunks
#define EPSF 1e-9f

// partial corrections: [NJY][NB] float2
__device__ float2 g_partial[NJY * NB];
__device__ int    g_cnt[ITILES] = {};

__device__ __forceinline__ float rsq_approx(float x) {
    float r;
    asm("rsqrt.approx.f32 %0, %1;" : "=f"(r) : "f"(x));
    return r;
}

__global__ void __launch_bounds__(TPB)
collide_kernel(const float* __restrict__ cpos, const float* __restrict__ crad,
               const float* __restrict__ apos, const float* __restrict__ ahalf,
               float* __restrict__ out)
{
    __shared__ float4 sj[TPB];   // circle j: (x, y, 0.5*r, --) ; aabb j: (x, y, hx, hy)
    __shared__ int s_old;

    const int tid = threadIdx.x;
    const int bx  = blockIdx.x;                 // i-tile
    const int i   = bx * TPB + tid;             // body index 0..NB-1
    const bool i_is_circle = (i < NC);
    const int jy = blockIdx.y;
    const bool j_is_circle = (jy < NCY);
    const int j0 = j_is_circle ? (jy * TPB) : ((jy - NCY) * TPB);

    // stage j bodies (one per thread)
    {
        if (j_is_circle) {
            float2 p = ((const float2*)cpos)[j0 + tid];
            sj[tid] = make_float4(p.x, p.y, 0.5f * crad[j0 + tid], 0.0f);
        } else {
            float2 p = ((const float2*)apos)[j0 + tid];
            float2 h = ((const float2*)ahalf)[j0 + tid];
            sj[tid] = make_float4(p.x, p.y, h.x, h.y);
        }
    }

    // hoisted i-state
    float pix, piy, ra, rb;      // circle: ra=0.5*r ; aabb: ra=hx, rb=hy
    int ia = 0;
    if (i_is_circle) {
        float2 p = ((const float2*)cpos)[i];
        pix = p.x; piy = p.y;
        ra = 0.5f * crad[i]; rb = 0.0f;
    } else {
        ia = i - NC;
        float2 p = ((const float2*)apos)[ia];
        float2 h = ((const float2*)ahalf)[ia];
        pix = p.x; piy = p.y;
        ra = h.x; rb = h.y;
    }

    __syncthreads();

    float cx = 0.0f, cy = 0.0f;

    if (i_is_circle) {
        if (j_is_circle) {
            // circle vs circle:  s = 0.5*(rsum-dist)/dist ; pen>0 <=> s>0
            #pragma unroll 8
            for (int k = 0; k < TPB; k++) {
                float4 b = sj[k];
                float dx = pix - b.x;
                float dy = piy - b.y;
                float d2 = fmaf(dx, dx, dy * dy);
                float halfrsum = ra + b.z;               // 0.5*(ri+rj)
                float inv = rsq_approx(d2);
                float s = fmaf(halfrsum, inv, -0.5f);
                s = fmaxf(s, 0.0f);
                s = (d2 > EPSF) ? s : 0.0f;
                cx = fmaf(s, dx, cx);
                cy = fmaf(s, dy, cy);
            }
        } else {
            // circle vs aabb (push on circle)
            #pragma unroll 8
            for (int k = 0; k < TPB; k++) {
                float4 b = sj[k];
                float relx = pix - b.x;
                float rely = piy - b.y;
                float qx = fminf(fmaxf(relx, -b.z), b.z);
                float qy = fminf(fmaxf(rely, -b.w), b.w);
                float dx = relx - qx;
                float dy = rely - qy;
                float dd2 = fmaf(dx, dx, dy * dy);
                float inv = rsq_approx(dd2);
                float s = fmaf(ra, inv, -0.5f);          // ra = 0.5*ri
                s = fmaxf(s, 0.0f);
                s = (dd2 > EPSF) ? s : 0.0f;
                cx = fmaf(s, dx, cx);
                cy = fmaf(s, dy, cy);
            }
        }
    } else {
        if (j_is_circle) {
            // aabb vs circle (equal-and-opposite push on aabb)
            #pragma unroll 8
            for (int k = 0; k < TPB; k++) {
                float4 b = sj[k];
                float relx = b.x - pix;                  // circle - aabb
                float rely = b.y - piy;
                float qx = fminf(fmaxf(relx, -ra), ra);  // ra=hx
                float qy = fminf(fmaxf(rely, -rb), rb);  // rb=hy
                float dx = relx - qx;
                float dy = rely - qy;
                float dd2 = fmaf(dx, dx, dy * dy);
                float inv = rsq_approx(dd2);
                float s = fmaf(b.z, inv, -0.5f);         // b.z = 0.5*rj
                s = fmaxf(s, 0.0f);
                s = (dd2 > EPSF) ? s : 0.0f;
                cx = fmaf(-s, dx, cx);                   // negated push on box
                cy = fmaf(-s, dy, cy);
            }
        } else {
            // aabb vs aabb
            #pragma unroll 8
            for (int k = 0; k < TPB; k++) {
                float4 b = sj[k];
                int j = j0 + k;
                float dax = pix - b.x;
                float day = piy - b.y;
                float ovx = (ra + b.z) - fabsf(dax);
                float ovy = (rb + b.w) - fabsf(day);
                bool hit = (ovx > 0.0f) && (ovy > 0.0f) && (ia != j);
                bool usex = (ovx <= ovy);
                float px = copysignf(0.5f * ovx, dax);   // sgn(+0)=+1 matches da>=0
                float py = copysignf(0.5f * ovy, day);
                cx += (hit && usex)  ? px : 0.0f;
                cy += (hit && !usex) ? py : 0.0f;
            }
        }
    }

    g_partial[(size_t)jy * NB + i] = make_float2(cx, cy);

    // ---- last-arriving block of this i-tile folds all 24 partials ----
    __threadfence();                       // release partial write
    if (tid == 0) s_old = atomicAdd(&g_cnt[bx], 1);
    __syncthreads();
    if (s_old == NJY - 1) {
        __threadfence();                   // acquire: see all partials from L2
        float2 base = i_is_circle ? ((const float2*)cpos)[i]
                                  : ((const float2*)apos)[i - NC];
        float sx = base.x, sy = base.y;
        #pragma unroll
        for (int y = 0; y < NJY; y++) {    // fixed order => deterministic
            float2 p = g_partial[(size_t)y * NB + i];
            sx += p.x; sy += p.y;
        }
        ((float2*)out)[i] = make_float2(sx, sy);
        if (tid == 0) g_cnt[bx] = 0;       // reset for next graph replay
    }
}

extern "C" void kernel_launch(void* const* d_in, const int* in_sizes, int n_in,
                              void* d_out, int out_size)
{
    const float* cpos  = (const float*)d_in[0];   // [4096,2]
    const float* crad  = (const float*)d_in[1];   // [4096]
    const float* apos  = (const float*)d_in[2];   // [2048,2]
    const float* ahalf = (const float*)d_in[3];   // [2048,2]
    float* out = (float*)d_out;                   // [6144,2]

    dim3 grid(ITILES, NJY);
    collide_kernel<<<grid, TPB>>>(cpos, crad, apos, ahalf, out);
}

// round 7
// speedup vs baseline: 1.4848x; 1.1391x over previous
#include <cuda_runtime.h>

#define NC 4096
#define NA 2048
#define NB (NC + NA)          // 6144 bodies
#define TPB 128
#define CHUNK 256             // j-chunk size
#define ITILES (NB / TPB)     // 48 i-tiles
#define NCY (NC / CHUNK)      // 16 circle j-chunks
#define NAY (NA / CHUNK)      // 8 aabb j-chunks
#define NJY (NCY + NAY)       // 24 j-chunks
#define EPSF 1e-9f

// partial corrections: [NJY][NB] float2
__device__ float2 g_partial[NJY * NB];
__device__ int    g_cnt[ITILES] = {};

typedef unsigned long long u64;

__device__ __forceinline__ float rsq_approx(float x) {
    float r;
    asm("rsqrt.approx.f32 %0, %1;" : "=f"(r) : "f"(x));
    return r;
}
__device__ __forceinline__ u64 pack2(float lo, float hi) {
    u64 r; asm("mov.b64 %0, {%1, %2};" : "=l"(r) : "f"(lo), "f"(hi)); return r;
}
__device__ __forceinline__ void unpack2(u64 v, float& lo, float& hi) {
    asm("mov.b64 {%0, %1}, %2;" : "=f"(lo), "=f"(hi) : "l"(v));
}
__device__ __forceinline__ u64 add2(u64 a, u64 b) {
    u64 r; asm("add.rn.f32x2 %0, %1, %2;" : "=l"(r) : "l"(a), "l"(b)); return r;
}
__device__ __forceinline__ u64 mul2(u64 a, u64 b) {
    u64 r; asm("mul.rn.f32x2 %0, %1, %2;" : "=l"(r) : "l"(a), "l"(b)); return r;
}
__device__ __forceinline__ u64 fma2(u64 a, u64 b, u64 c) {
    u64 r; asm("fma.rn.f32x2 %0, %1, %2, %3;" : "=l"(r) : "l"(a), "l"(b), "l"(c)); return r;
}

__global__ void __launch_bounds__(TPB)
collide_kernel(const float* __restrict__ cpos, const float* __restrict__ crad,
               const float* __restrict__ apos, const float* __restrict__ ahalf,
               float* __restrict__ out)
{
    __shared__ float2 spos[CHUNK];   // NEGATED j position
    __shared__ float2 saux[CHUNK];   // circle j: (0.5*r, --) ; aabb j: (hx, hy)
    __shared__ int s_old;

    const int tid = threadIdx.x;
    const int bx  = blockIdx.x;                 // i-tile
    const int i   = bx * TPB + tid;             // body index 0..NB-1
    const bool i_is_circle = (i < NC);
    const int jy = blockIdx.y;
    const bool j_is_circle = (jy < NCY);
    const int j0 = j_is_circle ? (jy * CHUNK) : ((jy - NCY) * CHUNK);

    // stage CHUNK j-bodies (2 per thread), positions negated
    #pragma unroll
    for (int t = tid; t < CHUNK; t += TPB) {
        if (j_is_circle) {
            float2 p = ((const float2*)cpos)[j0 + t];
            spos[t] = make_float2(-p.x, -p.y);
            saux[t] = make_float2(0.5f * crad[j0 + t], 0.0f);
        } else {
            float2 p = ((const float2*)apos)[j0 + t];
            spos[t] = make_float2(-p.x, -p.y);
            saux[t] = ((const float2*)ahalf)[j0 + t];
        }
    }

    // hoisted i-state
    float pix, piy, ra, rb;      // circle: ra=0.5*r ; aabb: ra=hx, rb=hy
    int ia = 0;
    if (i_is_circle) {
        float2 p = ((const float2*)cpos)[i];
        pix = p.x; piy = p.y;
        ra = 0.5f * crad[i]; rb = 0.0f;
    } else {
        ia = i - NC;
        float2 p = ((const float2*)apos)[ia];
        float2 h = ((const float2*)ahalf)[ia];
        pix = p.x; piy = p.y;
        ra = h.x; rb = h.y;
    }
    const u64 pixy = pack2(pix, piy);
    const u64* spos64 = (const u64*)spos;

    __syncthreads();

    u64 acc = pack2(0.0f, 0.0f);

    if (i_is_circle) {
        if (j_is_circle) {
            // circle vs circle: s = 0.5*(rsum-dist)/dist, clamped >=0.
            // Gateless: d2 clamped to EPS => self-pair (d=+0) contributes exactly 0.
            #pragma unroll 8
            for (int k = 0; k < CHUNK; k++) {
                u64 d = add2(pixy, spos64[k]);      // (dx,dy) = pi - pj
                u64 sq = mul2(d, d);
                float sx, sy; unpack2(sq, sx, sy);
                float d2 = fmaxf(sx + sy, EPSF);
                float inv = rsq_approx(d2);
                float s = fmaf(ra + saux[k].x, inv, -0.5f);   // halfrsum*inv - 0.5
                s = fmaxf(s, 0.0f);
                acc = fma2(pack2(s, s), d, acc);
            }
        } else {
            // circle vs aabb (push on circle)
            #pragma unroll 8
            for (int k = 0; k < CHUNK; k++) {
                u64 rel = add2(pixy, spos64[k]);    // ci - aj
                float rx, ry; unpack2(rel, rx, ry);
                float2 h = saux[k];
                float qx = fminf(fmaxf(rx, -h.x), h.x);
                float qy = fminf(fmaxf(ry, -h.y), h.y);
                float dx = rx - qx;
                float dy = ry - qy;
                float dd2 = fmaxf(fmaf(dx, dx, dy * dy), EPSF);
                float inv = rsq_approx(dd2);
                float s = fmaf(ra, inv, -0.5f);     // ra = 0.5*ri
                s = fmaxf(s, 0.0f);
                acc = fma2(pack2(s, s), pack2(dx, dy), acc);
            }
        }
    } else {
        if (j_is_circle) {
            // aabb vs circle. rel' = ai - cj = -rel  =>  box push = +s*diff'
            #pragma unroll 8
            for (int k = 0; k < CHUNK; k++) {
                u64 rel = add2(pixy, spos64[k]);    // ai - cj
                float rx, ry; unpack2(rel, rx, ry);
                float qx = fminf(fmaxf(rx, -ra), ra);   // ra=hx
                float qy = fminf(fmaxf(ry, -rb), rb);   // rb=hy
                float dx = rx - qx;
                float dy = ry - qy;
                float dd2 = fmaxf(fmaf(dx, dx, dy * dy), EPSF);
                float inv = rsq_approx(dd2);
                float s = fmaf(saux[k].x, inv, -0.5f);  // 0.5*rj*inv - 0.5
                s = fmaxf(s, 0.0f);
                acc = fma2(pack2(s, s), pack2(dx, dy), acc);
            }
        } else {
            // aabb vs aabb
            float cx = 0.0f, cy = 0.0f;
            #pragma unroll 8
            for (int k = 0; k < CHUNK; k++) {
                u64 da = add2(pixy, spos64[k]);     // ai - aj
                float dax, day; unpack2(da, dax, day);
                float2 h = saux[k];
                float ovx = (ra + h.x) - fabsf(dax);
                float ovy = (rb + h.y) - fabsf(day);
                bool hit = (ovx > 0.0f) && (ovy > 0.0f) && (ia != (j0 + k));
                bool usex = (ovx <= ovy);
                float px = copysignf(0.5f * ovx, dax);   // sgn(+0)=+1 matches da>=0
                float py = copysignf(0.5f * ovy, day);
                cx += (hit && usex)  ? px : 0.0f;
                cy += (hit && !usex) ? py : 0.0f;
            }
            acc = pack2(cx, cy);
        }
    }

    {
        float ax, ay; unpack2(acc, ax, ay);
        g_partial[(size_t)jy * NB + i] = make_float2(ax, ay);
    }

    // ---- last-arriving block of this i-tile folds all partials (fixed order) ----
    __threadfence();                       // release partial write
    if (tid == 0) s_old = atomicAdd(&g_cnt[bx], 1);
    __syncthreads();
    if (s_old == NJY - 1) {
        __threadfence();                   // see all partials
        float2 base = i_is_circle ? ((const float2*)cpos)[i]
                                  : ((const float2*)apos)[i - NC];
        float sx = base.x, sy = base.y;
        #pragma unroll
        for (int y = 0; y < NJY; y++) {    // fixed order => deterministic
            float2 p = g_partial[(size_t)y * NB + i];
            sx += p.x; sy += p.y;
        }
        ((float2*)out)[i] = make_float2(sx, sy);
        if (tid == 0) g_cnt[bx] = 0;       // reset for next graph replay
    }
}

extern "C" void kernel_launch(void* const* d_in, const int* in_sizes, int n_in,
                              void* d_out, int out_size)
{
    const float* cpos  = (const float*)d_in[0];   // [4096,2]
    const float* crad  = (const float*)d_in[1];   // [4096]
    const float* apos  = (const float*)d_in[2];   // [2048,2]
    const float* ahalf = (const float*)d_in[3];   // [2048,2]
    float* out = (float*)d_out;                   // [6144,2]

    dim3 grid(ITILES, NJY);
    collide_kernel<<<grid, TPB>>>(cpos, crad, apos, ahalf, out);
}